// round 12
// baseline (speedup 1.0000x reference)
#include <cuda_runtime.h>
#include <cuda_bf16.h>
#include <cstdint>
#include <math.h>

#define MAX_N 500000
#define MAX_E 1000000
#define HDIM  64
#define SCAN_T 512
#define SCAN_ITEMS 1024
#define POOL_BLOCKS 2960

// ---------------- device scratch ----------------
__device__ __nv_bfloat16 g_m0[(size_t)MAX_N * HDIM];  // layer-2 messages (bf16)
__device__ __nv_bfloat16 g_m1[(size_t)MAX_N * HDIM];  // layer-3 messages (bf16)
__device__ float g_dinv[MAX_N];
__device__ float4 g_xs4[MAX_N];
__device__ int   g_degi[MAX_N];
__device__ int   g_rowptr[MAX_N + 1];
__device__ int   g_cursor[MAX_N];
__device__ int   g_esrc[MAX_E];
__device__ unsigned long long g_lb[512];   // lookback state: (flag<<32)|value
__device__ unsigned g_lbctr;
__device__ float g_partial[(size_t)POOL_BLOCKS * HDIM];
__device__ float g_pool[HDIM];

// ---------------- helpers ----------------
__device__ __forceinline__ unsigned pack_bf16x2(float lo, float hi) {
    unsigned r;
    asm("cvt.rn.bf16x2.f32 %0, %1, %2;" : "=r"(r) : "f"(hi), "f"(lo));
    return r;
}
__device__ __forceinline__ void acc_bf16x2(float& a0, float& a1, unsigned v) {
    __nv_bfloat162 b = *reinterpret_cast<__nv_bfloat162*>(&v);
    float2 f = __bfloat1622float2(b);
    a0 += f.x; a1 += f.y;
}
__device__ __forceinline__ void acc_uint4(float* a, uint4 v) {
    acc_bf16x2(a[0], a[1], v.x);
    acc_bf16x2(a[2], a[3], v.y);
    acc_bf16x2(a[4], a[5], v.z);
    acc_bf16x2(a[6], a[7], v.w);
}
__device__ __forceinline__ uint32_t f2tf32(float f) {
    uint32_t r;
    asm("cvt.rna.tf32.f32 %0, %1;" : "=r"(r) : "f"(f));
    return r;
}
__device__ __forceinline__ void mma_tf32(float* d, uint32_t a0, uint32_t a1, uint32_t a2,
                                         uint32_t a3, uint32_t b0, uint32_t b1) {
    asm volatile("mma.sync.aligned.m16n8k8.row.col.f32.tf32.tf32.f32 "
                 "{%0,%1,%2,%3}, {%4,%5,%6,%7}, {%8,%9}, {%0,%1,%2,%3};"
                 : "+f"(d[0]), "+f"(d[1]), "+f"(d[2]), "+f"(d[3])
                 : "r"(a0), "r"(a1), "r"(a2), "r"(a3), "r"(b0), "r"(b1));
}

#define AROW 68   // fp32/tf32 smem row stride (u32)

// ---------------- init ----------------
__global__ void k_zero(int N) {
    int i = blockIdx.x * blockDim.x + threadIdx.x;
    if (i < N) { g_degi[i] = 0; g_cursor[i] = 0; }
    if (i < 512) g_lb[i] = 0ull;
    if (i == 0) g_lbctr = 0u;
}

__global__ void k_hist(const int* __restrict__ ei, int E) {
    int e = blockIdx.x * blockDim.x + threadIdx.x;
    if (e < E) atomicAdd(&g_degi[ei[E + e]], 1);
}

// ---------------- single-pass scan (decoupled lookback) + dinv/xs prep ----------------
__global__ __launch_bounds__(SCAN_T) void k_scan_fused(const float* __restrict__ x,
                                                       int N, int E) {
    __shared__ int sdata[SCAN_T];
    __shared__ int s_bid;
    __shared__ int s_prev;
    if (threadIdx.x == 0) s_bid = (int)atomicAdd(&g_lbctr, 1u);
    __syncthreads();
    int bid = s_bid;
    int base = bid * SCAN_ITEMS;
    int i0 = base + threadIdx.x * 2;
    int d0 = (i0     < N) ? g_degi[i0]     : 0;
    int d1 = (i0 + 1 < N) ? g_degi[i0 + 1] : 0;
    int tsum = d0 + d1;
    sdata[threadIdx.x] = tsum;
    __syncthreads();
    for (int off = 1; off < SCAN_T; off <<= 1) {
        int v = (threadIdx.x >= off) ? sdata[threadIdx.x - off] : 0;
        __syncthreads();
        sdata[threadIdx.x] += v;
        __syncthreads();
    }
    int excl = sdata[threadIdx.x] - tsum;

    if (threadIdx.x == SCAN_T - 1) {
        int total = sdata[SCAN_T - 1];
        // publish local aggregate (flag 1)
        atomicExch(&g_lb[bid], (1ull << 32) | (unsigned)total);
        // lookback
        int prev = 0;
        for (int j = bid - 1; j >= 0; j--) {
            unsigned long long v;
            do { v = atomicAdd(&g_lb[j], 0ull); } while ((v >> 32) == 0ull);
            prev += (int)(unsigned)v;
            if ((v >> 32) == 2ull) break;     // that was an inclusive prefix
        }
        // publish inclusive prefix (flag 2)
        atomicExch(&g_lb[bid], (2ull << 32) | (unsigned)(prev + total));
        s_prev = prev;
        if (base + SCAN_ITEMS >= N) g_rowptr[N] = E;   // last logical block
    }
    __syncthreads();
    int prev = s_prev;

    // write rowptr + prep dinv/xs4 for this block's 2 elements
    if (i0 < N) {
        g_rowptr[i0] = prev + excl;
        float di = rsqrtf((float)(d0 + 1));
        g_dinv[i0] = di;
        g_xs4[i0] = make_float4(di * x[(size_t)i0 * 3 + 0],
                                di * x[(size_t)i0 * 3 + 1],
                                di * x[(size_t)i0 * 3 + 2], 0.0f);
    }
    if (i0 + 1 < N) {
        int i1 = i0 + 1;
        g_rowptr[i1] = prev + excl + d0;
        float di = rsqrtf((float)(d1 + 1));
        g_dinv[i1] = di;
        g_xs4[i1] = make_float4(di * x[(size_t)i1 * 3 + 0],
                                di * x[(size_t)i1 * 3 + 1],
                                di * x[(size_t)i1 * 3 + 2], 0.0f);
    }
}

__global__ void k_fill(const int* __restrict__ ei, int E) {
    int e = blockIdx.x * blockDim.x + threadIdx.x;
    if (e >= E) return;
    int s = ei[e];
    int d = ei[E + e];
    int pos = g_rowptr[d] + atomicAdd(&g_cursor[d], 1);
    g_esrc[pos] = s;
}

// ---------------- tf32 tensor-core GEMM phase ----------------
__device__ __forceinline__ void gemm_mma(const uint32_t* sA, const uint32_t* sB,
                                         uint32_t* sC, const float* sdinv,
                                         __nv_bfloat16* outBuf, int nodeBase, int N) {
    int tid  = threadIdx.x;
    int w    = tid >> 5;
    int lane = tid & 31;
    int mw = w & 3;
    int nw = w >> 2;
    int g  = lane >> 2;
    int t  = lane & 3;

    float d[4][4];
    #pragma unroll
    for (int i = 0; i < 4; i++)
        #pragma unroll
        for (int j = 0; j < 4; j++) d[i][j] = 0.0f;

    const uint32_t* aRow0 = sA + (mw * 16 + g) * AROW;
    const uint32_t* aRow1 = aRow0 + 8 * AROW;
    int nbase = nw * 32 + g;

    #pragma unroll
    for (int kt = 0; kt < 8; kt++) {
        int k0 = kt * 8 + t;
        uint32_t a0 = aRow0[k0];
        uint32_t a1 = aRow1[k0];
        uint32_t a2 = aRow0[k0 + 4];
        uint32_t a3 = aRow1[k0 + 4];
        const uint32_t* b0p = sB + k0 * AROW + nbase;
        const uint32_t* b1p = b0p + 4 * AROW;
        #pragma unroll
        for (int nt = 0; nt < 4; nt++) {
            mma_tf32(d[nt], a0, a1, a2, a3, b0p[nt * 8], b1p[nt * 8]);
        }
    }

    int r0 = mw * 16 + g;
    int r1 = r0 + 8;
    float di0 = sdinv[r0], di1 = sdinv[r1];
    #pragma unroll
    for (int nt = 0; nt < 4; nt++) {
        int cp = nw * 16 + nt * 4 + t;
        sC[r0 * 36 + cp] = pack_bf16x2(d[nt][0] * di0, d[nt][1] * di0);
        sC[r1 * 36 + cp] = pack_bf16x2(d[nt][2] * di1, d[nt][3] * di1);
    }
    __syncthreads();

    int r = tid >> 2, q = tid & 3;
    if (nodeBase + r < N) {
        uint4 v0 = *(uint4*)&sC[r * 36 + q * 8];
        uint4 v1 = *(uint4*)&sC[r * 36 + q * 8 + 4];
        __nv_bfloat16* o = outBuf + (size_t)(nodeBase + r) * HDIM + q * 16;
        *(uint4*)o       = v0;
        *((uint4*)o + 1) = v1;
    }
}

__device__ __forceinline__ void load_W_tf32(const float* __restrict__ W, uint32_t* sB) {
    int tid = threadIdx.x;
    #pragma unroll
    for (int i = tid; i < 1024; i += 256) {
        int k = i >> 4, cq = i & 15;
        float4 wv = ((const float4*)W)[i];
        uint32_t* o = sB + k * AROW + cq * 4;
        o[0] = f2tf32(wv.x); o[1] = f2tf32(wv.y);
        o[2] = f2tf32(wv.z); o[3] = f2tf32(wv.w);
    }
}

__device__ __forceinline__ void load_dinv(float* sdinv, int nodeBase, int N) {
    int tid = threadIdx.x;
    if (tid >= 64 && tid < 128) {
        int n = nodeBase + tid - 64;
        sdinv[tid - 64] = (n < N) ? g_dinv[n] : 0.0f;
    }
}

// ---------------- kA: fused x-aggregation + layer-1 + layer-2 transforms -> m0 ----------------
__global__ __launch_bounds__(256) void kA_l12(const float* __restrict__ W1,
                                              const float* __restrict__ b1,
                                              const float* __restrict__ W2, int N) {
    __shared__ __align__(16) uint32_t sA[64 * AROW];
    __shared__ __align__(16) uint32_t sB[64 * AROW];
    __shared__ __align__(16) uint32_t sC[64 * 36];
    __shared__ float4 sxa[64];
    __shared__ float sW1[192];
    __shared__ float sb1[64];
    __shared__ float sdinv[64];
    int tid = threadIdx.x;
    int nodeBase = blockIdx.x * 64;

    if (tid < 64) {
        int d = nodeBase + tid;
        float4 a = make_float4(0.f, 0.f, 0.f, 0.f);
        float di = 0.0f;
        if (d < N) {
            a = g_xs4[d];
            int i = g_rowptr[d], end = g_rowptr[d + 1];
            for (; i + 2 <= end; i += 2) {
                int s0 = g_esrc[i], s1 = g_esrc[i + 1];
                float4 v0 = g_xs4[s0];
                float4 v1 = g_xs4[s1];
                a.x += v0.x + v1.x; a.y += v0.y + v1.y; a.z += v0.z + v1.z;
            }
            if (i < end) {
                float4 v = g_xs4[g_esrc[i]];
                a.x += v.x; a.y += v.y; a.z += v.z;
            }
            di = g_dinv[d];
        }
        sxa[tid] = make_float4(di * a.x, di * a.y, di * a.z, 0.0f);
    }
    if (tid >= 192) {
        int j = tid - 192;
        if (j < 64) sb1[j] = b1[j];
    }
    if (tid >= 128 && tid < 192) {
        sW1[tid - 128] = W1[tid - 128];
        sW1[tid - 64]  = W1[tid - 64];
        sW1[tid]       = W1[tid];
    }
    load_dinv(sdinv, nodeBase, N);
    load_W_tf32(W2, sB);
    __syncthreads();

    #pragma unroll
    for (int i = tid; i < 4096; i += 256) {
        int n = i >> 6, c = i & 63;
        float4 xa = sxa[n];
        float v = sb1[c] + xa.x * sW1[c] + xa.y * sW1[64 + c] + xa.z * sW1[128 + c];
        sA[n * AROW + c] = f2tf32(fmaxf(v, 0.0f));
    }
    __syncthreads();

    gemm_mma(sA, sB, sC, sdinv, g_m0, nodeBase, N);
}

// ---------------- kB: fused layer-2 aggregation + layer-3 transform -> m1 ----------------
__global__ __launch_bounds__(256) void kB_agg_tr(const float* __restrict__ b2,
                                                 const float* __restrict__ W3, int N) {
    __shared__ __align__(16) uint32_t sA[64 * AROW];
    __shared__ __align__(16) uint32_t sB[64 * AROW];
    __shared__ __align__(16) uint32_t sC[64 * 36];
    __shared__ float sb2[64];
    __shared__ float sdinv[64];
    int tid = threadIdx.x;
    int nodeBase = blockIdx.x * 64;

    if (tid < 64) sb2[tid] = b2[tid];
    load_dinv(sdinv, nodeBase, N);
    load_W_tf32(W3, sB);

    {
        int w    = tid >> 5;
        int lane = tid & 31;
        int oct  = lane >> 3;
        int l8   = lane & 7;
        #pragma unroll
        for (int j = 0; j < 2; j++) {
            int nl = w * 8 + j * 4 + oct;
            int d  = nodeBase + nl;
            float a[8] = {0.f, 0.f, 0.f, 0.f, 0.f, 0.f, 0.f, 0.f};
            float di = 0.0f;
            if (d < N) {
                acc_uint4(a, ((const uint4*)(g_m0 + (size_t)d * HDIM))[l8]);
                int i = g_rowptr[d], end = g_rowptr[d + 1];
                for (; i + 2 <= end; i += 2) {
                    int s0 = g_esrc[i], s1 = g_esrc[i + 1];
                    uint4 u0 = ((const uint4*)(g_m0 + (size_t)s0 * HDIM))[l8];
                    uint4 u1 = ((const uint4*)(g_m0 + (size_t)s1 * HDIM))[l8];
                    acc_uint4(a, u0);
                    acc_uint4(a, u1);
                }
                if (i < end) {
                    int s = g_esrc[i];
                    acc_uint4(a, ((const uint4*)(g_m0 + (size_t)s * HDIM))[l8]);
                }
                di = g_dinv[d];
            }
            const float* bb = &sb2[l8 * 8];
            uint32_t* o = sA + nl * AROW + l8 * 8;
            #pragma unroll
            for (int k = 0; k < 8; k++)
                o[k] = f2tf32(fmaxf(bb[k] + di * a[k], 0.f));
        }
    }
    __syncthreads();

    gemm_mma(sA, sB, sC, sdinv, g_m1, nodeBase, N);
}

// ---------------- kC: fused layer-3 aggregation + relu + pool partials ----------------
__global__ __launch_bounds__(256) void kC_agg_pool(const float* __restrict__ b, int N) {
    int tid  = threadIdx.x;
    int w    = tid >> 5;
    int lane = tid & 31;
    int oct  = lane >> 3;
    int l8   = lane & 7;

    float bb[8];
    #pragma unroll
    for (int k = 0; k < 8; k++) bb[k] = b[l8 * 8 + k];
    float acc[8] = {0.f, 0.f, 0.f, 0.f, 0.f, 0.f, 0.f, 0.f};

    int stride = gridDim.x * 32;
    for (int d = blockIdx.x * 32 + w * 4 + oct; d < N; d += stride) {
        float a[8] = {0.f, 0.f, 0.f, 0.f, 0.f, 0.f, 0.f, 0.f};
        acc_uint4(a, ((const uint4*)(g_m1 + (size_t)d * HDIM))[l8]);
        int i = g_rowptr[d], end = g_rowptr[d + 1];
        for (; i + 2 <= end; i += 2) {
            int s0 = g_esrc[i], s1 = g_esrc[i + 1];
            uint4 u0 = ((const uint4*)(g_m1 + (size_t)s0 * HDIM))[l8];
            uint4 u1 = ((const uint4*)(g_m1 + (size_t)s1 * HDIM))[l8];
            acc_uint4(a, u0);
            acc_uint4(a, u1);
        }
        if (i < end) {
            int s = g_esrc[i];
            acc_uint4(a, ((const uint4*)(g_m1 + (size_t)s * HDIM))[l8]);
        }
        float di = g_dinv[d];
        #pragma unroll
        for (int k = 0; k < 8; k++)
            acc[k] += fmaxf(bb[k] + di * a[k], 0.f);
    }

    __shared__ float sp[64];
    if (tid < 64) sp[tid] = 0.0f;
    __syncthreads();
    #pragma unroll
    for (int k = 0; k < 8; k++)
        atomicAdd(&sp[l8 * 8 + k], acc[k]);
    __syncthreads();
    if (tid < 64) g_partial[(size_t)blockIdx.x * HDIM + tid] = sp[tid];
}

// ---------------- merged reduce + FC + tanh (single block) ----------------
__global__ __launch_bounds__(256) void k_reduce_final(const float* __restrict__ Wfc,
                                                      const float* __restrict__ bfc,
                                                      float* __restrict__ out,
                                                      int N, int numPartial) {
    __shared__ float sp[256];
    int t = threadIdx.x;
    int c = t & 63, seg = t >> 6;   // 4 segments per channel
    float s = 0.0f;
    for (int i = seg; i < numPartial; i += 4)
        s += g_partial[(size_t)i * HDIM + c];
    sp[t] = s;
    __syncthreads();
    if (t < 64)
        g_pool[t] = sp[t] + sp[t + 64] + sp[t + 128] + sp[t + 192];
    __syncthreads();
    if (t < 24) {
        float invN = 1.0f / (float)N;
        float acc = bfc[t];
        #pragma unroll
        for (int k = 0; k < 64; k++)
            acc += (g_pool[k] * invN) * Wfc[k * 24 + t];
        out[t] = tanhf(acc);
    }
}

// ---------------- launch ----------------
extern "C" void kernel_launch(void* const* d_in, const int* in_sizes, int n_in,
                              void* d_out, int out_size) {
    const float* x   = (const float*)d_in[0];
    const int*   ei  = (const int*)d_in[1];   // int32 (JAX x64 disabled)
    const float* W1  = (const float*)d_in[3];
    const float* b1  = (const float*)d_in[4];
    const float* W2  = (const float*)d_in[5];
    const float* b2  = (const float*)d_in[6];
    const float* W3  = (const float*)d_in[7];
    const float* b3  = (const float*)d_in[8];
    const float* Wfc = (const float*)d_in[9];
    const float* bfc = (const float*)d_in[10];
    float* out = (float*)d_out;

    int N = in_sizes[0] / 3;
    int E = in_sizes[1] / 2;

    const int T = 256;
    int nbN    = (N + T - 1) / T;
    int nbE    = (E + T - 1) / T;
    int nbTr   = (N + 63) / 64;
    int nbScan = (N + SCAN_ITEMS - 1) / SCAN_ITEMS;

    // CSR + normalization (launches 1-4)
    k_zero<<<nbN, T>>>(N);
    k_hist<<<nbE, T>>>(ei, E);
    k_scan_fused<<<nbScan, SCAN_T>>>(x, N, E);
    k_fill<<<nbE, T>>>(ei, E);

    // launch 5: fused x-agg + layer1 + layer2 transforms -> m0
    kA_l12<<<nbTr, T>>>(W1, b1, W2, N);

    // launch 6 (ncu-profiled slot): fused layer2 agg + layer3 transform -> m1
    kB_agg_tr<<<nbTr, T>>>(b2, W3, N);

    // launch 7: fused layer3 aggregation + relu + mean-pool
    kC_agg_pool<<<POOL_BLOCKS, T>>>(b3, N);

    // launch 8: reduce + FC + tanh
    k_reduce_final<<<1, 256>>>(Wfc, bfc, out, N, POOL_BLOCKS);
}

// round 13
// speedup vs baseline: 1.0364x; 1.0364x over previous
#include <cuda_runtime.h>
#include <cuda_bf16.h>
#include <cstdint>
#include <math.h>

#define MAX_N 500000
#define MAX_E 1000000
#define HDIM  64
#define SCAN_T 512
#define SCAN_ITEMS 1024
#define POOL_BLOCKS 2960

// ---------------- device scratch ----------------
__device__ __nv_bfloat16 g_m0[(size_t)MAX_N * HDIM];  // layer-2 messages (bf16)
__device__ __nv_bfloat16 g_m1[(size_t)MAX_N * HDIM];  // layer-3 messages (bf16)
__device__ float g_dinv[MAX_N];
__device__ float4 g_xs4[MAX_N];
__device__ int   g_degi[MAX_N];
__device__ int   g_rowptr[MAX_N + 1];
__device__ int   g_cursor[MAX_N];
__device__ int   g_esrc[MAX_E];
__device__ int   g_bsum[1024];
__device__ float g_partial[(size_t)POOL_BLOCKS * HDIM];
__device__ float g_pool[HDIM];

// ---------------- helpers ----------------
__device__ __forceinline__ unsigned pack_bf16x2(float lo, float hi) {
    unsigned r;
    asm("cvt.rn.bf16x2.f32 %0, %1, %2;" : "=r"(r) : "f"(hi), "f"(lo));
    return r;
}
__device__ __forceinline__ void acc_bf16x2(float& a0, float& a1, unsigned v) {
    __nv_bfloat162 b = *reinterpret_cast<__nv_bfloat162*>(&v);
    float2 f = __bfloat1622float2(b);
    a0 += f.x; a1 += f.y;
}
__device__ __forceinline__ void acc_uint4(float* a, uint4 v) {
    acc_bf16x2(a[0], a[1], v.x);
    acc_bf16x2(a[2], a[3], v.y);
    acc_bf16x2(a[4], a[5], v.z);
    acc_bf16x2(a[6], a[7], v.w);
}
__device__ __forceinline__ uint32_t f2tf32(float f) {
    uint32_t r;
    asm("cvt.rna.tf32.f32 %0, %1;" : "=r"(r) : "f"(f));
    return r;
}
__device__ __forceinline__ void mma_tf32(float* d, uint32_t a0, uint32_t a1, uint32_t a2,
                                         uint32_t a3, uint32_t b0, uint32_t b1) {
    asm volatile("mma.sync.aligned.m16n8k8.row.col.f32.tf32.tf32.f32 "
                 "{%0,%1,%2,%3}, {%4,%5,%6,%7}, {%8,%9}, {%0,%1,%2,%3};"
                 : "+f"(d[0]), "+f"(d[1]), "+f"(d[2]), "+f"(d[3])
                 : "r"(a0), "r"(a1), "r"(a2), "r"(a3), "r"(b0), "r"(b1));
}

#define AROW 68   // fp32/tf32 smem row stride (u32)

// ---------------- degree / CSR ----------------
// 2 edges per thread (e and e+half), both streams coalesced, ILP 2
__global__ void k_hist(const int* __restrict__ ei, int E) {
    int half = (E + 1) >> 1;
    int e = blockIdx.x * blockDim.x + threadIdx.x;
    if (e >= half) return;
    int d0 = ei[E + e];
    atomicAdd(&g_degi[d0], 1);
    int e1 = e + half;
    if (e1 < E) {
        int d1 = ei[E + e1];
        atomicAdd(&g_degi[d1], 1);
    }
}

__global__ __launch_bounds__(SCAN_T) void k_scan_local(int N) {
    __shared__ int sdata[SCAN_T];
    int base = blockIdx.x * SCAN_ITEMS;
    int i0 = base + threadIdx.x * 2;
    int d0 = (i0     < N) ? g_degi[i0]     : 0;
    int d1 = (i0 + 1 < N) ? g_degi[i0 + 1] : 0;
    int tsum = d0 + d1;
    sdata[threadIdx.x] = tsum;
    __syncthreads();
    for (int off = 1; off < SCAN_T; off <<= 1) {
        int v = (threadIdx.x >= off) ? sdata[threadIdx.x - off] : 0;
        __syncthreads();
        sdata[threadIdx.x] += v;
        __syncthreads();
    }
    int excl = sdata[threadIdx.x] - tsum;
    if (i0     < N) g_rowptr[i0]     = excl;
    if (i0 + 1 < N) g_rowptr[i0 + 1] = excl + d0;
    if (threadIdx.x == SCAN_T - 1) g_bsum[blockIdx.x] = sdata[SCAN_T - 1];
}

__global__ __launch_bounds__(SCAN_T) void k_scan_bsums(int B) {
    __shared__ int sdata[SCAN_T];
    int v = (threadIdx.x < B) ? g_bsum[threadIdx.x] : 0;
    sdata[threadIdx.x] = v;
    __syncthreads();
    for (int off = 1; off < SCAN_T; off <<= 1) {
        int p = (threadIdx.x >= off) ? sdata[threadIdx.x - off] : 0;
        __syncthreads();
        sdata[threadIdx.x] += p;
        __syncthreads();
    }
    if (threadIdx.x < B) g_bsum[threadIdx.x] = sdata[threadIdx.x] - v;
}

// merged: finish scan + compute dinv + scaled x rows
__global__ void k_scan_add_prep(const float* __restrict__ x, int N, int E) {
    int i = blockIdx.x * blockDim.x + threadIdx.x;
    if (i == 0) g_rowptr[N] = E;
    if (i >= N) return;
    g_rowptr[i] += g_bsum[i / SCAN_ITEMS];
    float di = rsqrtf((float)(g_degi[i] + 1));
    g_dinv[i] = di;
    g_xs4[i] = make_float4(di * x[(size_t)i * 3 + 0],
                           di * x[(size_t)i * 3 + 1],
                           di * x[(size_t)i * 3 + 2], 0.0f);
}

// 2 edges per thread, ILP 2 on the atomic+scatter chains
__global__ void k_fill(const int* __restrict__ ei, int E) {
    int half = (E + 1) >> 1;
    int e = blockIdx.x * blockDim.x + threadIdx.x;
    if (e >= half) return;
    int s0 = ei[e];
    int d0 = ei[E + e];
    int e1 = e + half;
    int s1 = 0, d1 = -1;
    if (e1 < E) { s1 = ei[e1]; d1 = ei[E + e1]; }
    int p0 = g_rowptr[d0] + atomicAdd(&g_cursor[d0], 1);
    int p1 = (d1 >= 0) ? g_rowptr[d1] + atomicAdd(&g_cursor[d1], 1) : 0;
    g_esrc[p0] = s0;
    if (d1 >= 0) g_esrc[p1] = s1;
}

// ---------------- tf32 tensor-core GEMM phase ----------------
__device__ __forceinline__ void gemm_mma(const uint32_t* sA, const uint32_t* sB,
                                         uint32_t* sC, const float* sdinv,
                                         __nv_bfloat16* outBuf, int nodeBase, int N) {
    int tid  = threadIdx.x;
    int w    = tid >> 5;
    int lane = tid & 31;
    int mw = w & 3;
    int nw = w >> 2;
    int g  = lane >> 2;
    int t  = lane & 3;

    float d[4][4];
    #pragma unroll
    for (int i = 0; i < 4; i++)
        #pragma unroll
        for (int j = 0; j < 4; j++) d[i][j] = 0.0f;

    const uint32_t* aRow0 = sA + (mw * 16 + g) * AROW;
    const uint32_t* aRow1 = aRow0 + 8 * AROW;
    int nbase = nw * 32 + g;

    #pragma unroll
    for (int kt = 0; kt < 8; kt++) {
        int k0 = kt * 8 + t;
        uint32_t a0 = aRow0[k0];
        uint32_t a1 = aRow1[k0];
        uint32_t a2 = aRow0[k0 + 4];
        uint32_t a3 = aRow1[k0 + 4];
        const uint32_t* b0p = sB + k0 * AROW + nbase;
        const uint32_t* b1p = b0p + 4 * AROW;
        #pragma unroll
        for (int nt = 0; nt < 4; nt++) {
            mma_tf32(d[nt], a0, a1, a2, a3, b0p[nt * 8], b1p[nt * 8]);
        }
    }

    int r0 = mw * 16 + g;
    int r1 = r0 + 8;
    float di0 = sdinv[r0], di1 = sdinv[r1];
    #pragma unroll
    for (int nt = 0; nt < 4; nt++) {
        int cp = nw * 16 + nt * 4 + t;
        sC[r0 * 36 + cp] = pack_bf16x2(d[nt][0] * di0, d[nt][1] * di0);
        sC[r1 * 36 + cp] = pack_bf16x2(d[nt][2] * di1, d[nt][3] * di1);
    }
    __syncthreads();

    int r = tid >> 2, q = tid & 3;
    if (nodeBase + r < N) {
        uint4 v0 = *(uint4*)&sC[r * 36 + q * 8];
        uint4 v1 = *(uint4*)&sC[r * 36 + q * 8 + 4];
        __nv_bfloat16* o = outBuf + (size_t)(nodeBase + r) * HDIM + q * 16;
        *(uint4*)o       = v0;
        *((uint4*)o + 1) = v1;
    }
}

__device__ __forceinline__ void load_W_tf32(const float* __restrict__ W, uint32_t* sB) {
    int tid = threadIdx.x;
    #pragma unroll
    for (int i = tid; i < 1024; i += 256) {
        int k = i >> 4, cq = i & 15;
        float4 wv = ((const float4*)W)[i];
        uint32_t* o = sB + k * AROW + cq * 4;
        o[0] = f2tf32(wv.x); o[1] = f2tf32(wv.y);
        o[2] = f2tf32(wv.z); o[3] = f2tf32(wv.w);
    }
}

__device__ __forceinline__ void load_dinv(float* sdinv, int nodeBase, int N) {
    int tid = threadIdx.x;
    if (tid >= 64 && tid < 128) {
        int n = nodeBase + tid - 64;
        sdinv[tid - 64] = (n < N) ? g_dinv[n] : 0.0f;
    }
}

// ---------------- kA: fused x-aggregation + layer-1 + layer-2 transforms -> m0 ----------------
__global__ __launch_bounds__(256) void kA_l12(const float* __restrict__ W1,
                                              const float* __restrict__ b1,
                                              const float* __restrict__ W2, int N) {
    __shared__ __align__(16) uint32_t sA[64 * AROW];
    __shared__ __align__(16) uint32_t sB[64 * AROW];
    __shared__ __align__(16) uint32_t sC[64 * 36];
    __shared__ float4 sxa[64];
    __shared__ float sW1[192];
    __shared__ float sb1[64];
    __shared__ float sdinv[64];
    int tid = threadIdx.x;
    int nodeBase = blockIdx.x * 64;

    if (tid < 64) {
        int d = nodeBase + tid;
        float4 a = make_float4(0.f, 0.f, 0.f, 0.f);
        float di = 0.0f;
        if (d < N) {
            a = g_xs4[d];
            int i = g_rowptr[d], end = g_rowptr[d + 1];
            for (; i + 2 <= end; i += 2) {
                int s0 = g_esrc[i], s1 = g_esrc[i + 1];
                float4 v0 = g_xs4[s0];
                float4 v1 = g_xs4[s1];
                a.x += v0.x + v1.x; a.y += v0.y + v1.y; a.z += v0.z + v1.z;
            }
            if (i < end) {
                float4 v = g_xs4[g_esrc[i]];
                a.x += v.x; a.y += v.y; a.z += v.z;
            }
            di = g_dinv[d];
        }
        sxa[tid] = make_float4(di * a.x, di * a.y, di * a.z, 0.0f);
    }
    if (tid >= 192) {
        int j = tid - 192;
        if (j < 64) sb1[j] = b1[j];
    }
    if (tid >= 128 && tid < 192) {
        sW1[tid - 128] = W1[tid - 128];
        sW1[tid - 64]  = W1[tid - 64];
        sW1[tid]       = W1[tid];
    }
    load_dinv(sdinv, nodeBase, N);
    load_W_tf32(W2, sB);
    __syncthreads();

    #pragma unroll
    for (int i = tid; i < 4096; i += 256) {
        int n = i >> 6, c = i & 63;
        float4 xa = sxa[n];
        float v = sb1[c] + xa.x * sW1[c] + xa.y * sW1[64 + c] + xa.z * sW1[128 + c];
        sA[n * AROW + c] = f2tf32(fmaxf(v, 0.0f));
    }
    __syncthreads();

    gemm_mma(sA, sB, sC, sdinv, g_m0, nodeBase, N);
}

// ---------------- kB: fused layer-2 aggregation + layer-3 transform -> m1 ----------------
__global__ __launch_bounds__(256) void kB_agg_tr(const float* __restrict__ b2,
                                                 const float* __restrict__ W3, int N) {
    __shared__ __align__(16) uint32_t sA[64 * AROW];
    __shared__ __align__(16) uint32_t sB[64 * AROW];
    __shared__ __align__(16) uint32_t sC[64 * 36];
    __shared__ float sb2[64];
    __shared__ float sdinv[64];
    int tid = threadIdx.x;
    int nodeBase = blockIdx.x * 64;

    if (tid < 64) sb2[tid] = b2[tid];
    load_dinv(sdinv, nodeBase, N);
    load_W_tf32(W3, sB);

    {
        int w    = tid >> 5;
        int lane = tid & 31;
        int oct  = lane >> 3;
        int l8   = lane & 7;
        #pragma unroll
        for (int j = 0; j < 2; j++) {
            int nl = w * 8 + j * 4 + oct;
            int d  = nodeBase + nl;
            float a[8] = {0.f, 0.f, 0.f, 0.f, 0.f, 0.f, 0.f, 0.f};
            float di = 0.0f;
            if (d < N) {
                acc_uint4(a, ((const uint4*)(g_m0 + (size_t)d * HDIM))[l8]);
                int i = g_rowptr[d], end = g_rowptr[d + 1];
                for (; i + 2 <= end; i += 2) {
                    int s0 = g_esrc[i], s1 = g_esrc[i + 1];
                    uint4 u0 = ((const uint4*)(g_m0 + (size_t)s0 * HDIM))[l8];
                    uint4 u1 = ((const uint4*)(g_m0 + (size_t)s1 * HDIM))[l8];
                    acc_uint4(a, u0);
                    acc_uint4(a, u1);
                }
                if (i < end) {
                    int s = g_esrc[i];
                    acc_uint4(a, ((const uint4*)(g_m0 + (size_t)s * HDIM))[l8]);
                }
                di = g_dinv[d];
            }
            const float* bb = &sb2[l8 * 8];
            uint32_t* o = sA + nl * AROW + l8 * 8;
            #pragma unroll
            for (int k = 0; k < 8; k++)
                o[k] = f2tf32(fmaxf(bb[k] + di * a[k], 0.f));
        }
    }
    __syncthreads();

    gemm_mma(sA, sB, sC, sdinv, g_m1, nodeBase, N);
}

// ---------------- kC: fused layer-3 aggregation + relu + pool partials ----------------
__global__ __launch_bounds__(256) void kC_agg_pool(const float* __restrict__ b, int N) {
    int tid  = threadIdx.x;
    int w    = tid >> 5;
    int lane = tid & 31;
    int oct  = lane >> 3;
    int l8   = lane & 7;

    float bb[8];
    #pragma unroll
    for (int k = 0; k < 8; k++) bb[k] = b[l8 * 8 + k];
    float acc[8] = {0.f, 0.f, 0.f, 0.f, 0.f, 0.f, 0.f, 0.f};

    int stride = gridDim.x * 32;
    for (int d = blockIdx.x * 32 + w * 4 + oct; d < N; d += stride) {
        float a[8] = {0.f, 0.f, 0.f, 0.f, 0.f, 0.f, 0.f, 0.f};
        acc_uint4(a, ((const uint4*)(g_m1 + (size_t)d * HDIM))[l8]);
        int i = g_rowptr[d], end = g_rowptr[d + 1];
        for (; i + 2 <= end; i += 2) {
            int s0 = g_esrc[i], s1 = g_esrc[i + 1];
            uint4 u0 = ((const uint4*)(g_m1 + (size_t)s0 * HDIM))[l8];
            uint4 u1 = ((const uint4*)(g_m1 + (size_t)s1 * HDIM))[l8];
            acc_uint4(a, u0);
            acc_uint4(a, u1);
        }
        if (i < end) {
            int s = g_esrc[i];
            acc_uint4(a, ((const uint4*)(g_m1 + (size_t)s * HDIM))[l8]);
        }
        float di = g_dinv[d];
        #pragma unroll
        for (int k = 0; k < 8; k++)
            acc[k] += fmaxf(bb[k] + di * a[k], 0.f);
    }

    __shared__ float sp[64];
    if (tid < 64) sp[tid] = 0.0f;
    __syncthreads();
    #pragma unroll
    for (int k = 0; k < 8; k++)
        atomicAdd(&sp[l8 * 8 + k], acc[k]);
    __syncthreads();
    if (tid < 64) g_partial[(size_t)blockIdx.x * HDIM + tid] = sp[tid];
}

// ---------------- merged reduce + FC + tanh (single block) ----------------
__global__ __launch_bounds__(256) void k_reduce_final(const float* __restrict__ Wfc,
                                                      const float* __restrict__ bfc,
                                                      float* __restrict__ out,
                                                      int N, int numPartial) {
    __shared__ float sp[256];
    int t = threadIdx.x;
    int c = t & 63, seg = t >> 6;
    float s = 0.0f;
    for (int i = seg; i < numPartial; i += 4)
        s += g_partial[(size_t)i * HDIM + c];
    sp[t] = s;
    __syncthreads();
    if (t < 64)
        g_pool[t] = sp[t] + sp[t + 64] + sp[t + 128] + sp[t + 192];
    __syncthreads();
    if (t < 24) {
        float invN = 1.0f / (float)N;
        float acc = bfc[t];
        #pragma unroll
        for (int k = 0; k < 64; k++)
            acc += (g_pool[k] * invN) * Wfc[k * 24 + t];
        out[t] = tanhf(acc);
    }
}

// ---------------- launch ----------------
extern "C" void kernel_launch(void* const* d_in, const int* in_sizes, int n_in,
                              void* d_out, int out_size) {
    const float* x   = (const float*)d_in[0];
    const int*   ei  = (const int*)d_in[1];   // int32 (JAX x64 disabled)
    const float* W1  = (const float*)d_in[3];
    const float* b1  = (const float*)d_in[4];
    const float* W2  = (const float*)d_in[5];
    const float* b2  = (const float*)d_in[6];
    const float* W3  = (const float*)d_in[7];
    const float* b3  = (const float*)d_in[8];
    const float* Wfc = (const float*)d_in[9];
    const float* bfc = (const float*)d_in[10];
    float* out = (float*)d_out;

    int N = in_sizes[0] / 3;
    int E = in_sizes[1] / 2;

    const int T = 256;
    int nbN    = (N + T - 1) / T;
    int nbE2   = ((E + 1) / 2 + T - 1) / T;
    int nbTr   = (N + 63) / 64;
    int nbScan = (N + SCAN_ITEMS - 1) / SCAN_ITEMS;

    // zero deg/cursor via memset (graph-capturable, allocation-free)
    void* degAddr = nullptr;
    void* curAddr = nullptr;
    cudaGetSymbolAddress(&degAddr, g_degi);
    cudaGetSymbolAddress(&curAddr, g_cursor);
    cudaMemsetAsync(degAddr, 0, (size_t)N * sizeof(int));
    cudaMemsetAsync(curAddr, 0, (size_t)N * sizeof(int));

    // CSR + normalization
    k_hist<<<nbE2, T>>>(ei, E);
    k_scan_local<<<nbScan, SCAN_T>>>(N);
    k_scan_bsums<<<1, SCAN_T>>>(nbScan);
    k_scan_add_prep<<<nbN, T>>>(x, N, E);
    k_fill<<<nbE2, T>>>(ei, E);

    // fused x-agg + layer1 + layer2 transforms -> m0 (tf32 tensor cores)
    kA_l12<<<nbTr, T>>>(W1, b1, W2, N);

    // fused layer2 aggregation + layer3 transform -> m1 (tf32 tensor cores)
    kB_agg_tr<<<nbTr, T>>>(b2, W3, N);

    // fused layer3 aggregation + relu + mean-pool
    kC_agg_pool<<<POOL_BLOCKS, T>>>(b3, N);

    // reduce + FC + tanh
    k_reduce_final<<<1, 256>>>(Wfc, bfc, out, N, POOL_BLOCKS);
}

// round 14
// speedup vs baseline: 1.0926x; 1.0542x over previous
#include <cuda_runtime.h>
#include <cuda_bf16.h>
#include <cstdint>
#include <math.h>

#define MAX_N 500000
#define MAX_E 1000000
#define HDIM  64
#define SCAN_T 512
#define SCAN_ITEMS 1024
#define POOL_BLOCKS 2960

// ---------------- device scratch ----------------
__device__ __nv_bfloat16 g_m0[(size_t)MAX_N * HDIM];  // layer-2 messages (bf16)
__device__ __nv_bfloat16 g_m1[(size_t)MAX_N * HDIM];  // layer-3 messages (bf16)
__device__ float g_dinv[MAX_N];
__device__ float4 g_xs4[MAX_N];
__device__ int   g_degi[MAX_N];
__device__ int   g_rowptr[MAX_N + 1];
__device__ int   g_erank[MAX_E];                      // per-edge rank within dst row
__device__ int   g_esrc[MAX_E];
__device__ int   g_bsum[1024];
__device__ float g_partial[(size_t)POOL_BLOCKS * HDIM];
__device__ float g_pool[HDIM];

// ---------------- helpers ----------------
__device__ __forceinline__ unsigned pack_bf16x2(float lo, float hi) {
    unsigned r;
    asm("cvt.rn.bf16x2.f32 %0, %1, %2;" : "=r"(r) : "f"(hi), "f"(lo));
    return r;
}
__device__ __forceinline__ void acc_bf16x2(float& a0, float& a1, unsigned v) {
    __nv_bfloat162 b = *reinterpret_cast<__nv_bfloat162*>(&v);
    float2 f = __bfloat1622float2(b);
    a0 += f.x; a1 += f.y;
}
__device__ __forceinline__ void acc_uint4(float* a, uint4 v) {
    acc_bf16x2(a[0], a[1], v.x);
    acc_bf16x2(a[2], a[3], v.y);
    acc_bf16x2(a[4], a[5], v.z);
    acc_bf16x2(a[6], a[7], v.w);
}
__device__ __forceinline__ uint32_t f2tf32(float f) {
    uint32_t r;
    asm("cvt.rna.tf32.f32 %0, %1;" : "=r"(r) : "f"(f));
    return r;
}
__device__ __forceinline__ void mma_tf32(float* d, uint32_t a0, uint32_t a1, uint32_t a2,
                                         uint32_t a3, uint32_t b0, uint32_t b1) {
    asm volatile("mma.sync.aligned.m16n8k8.row.col.f32.tf32.tf32.f32 "
                 "{%0,%1,%2,%3}, {%4,%5,%6,%7}, {%8,%9}, {%0,%1,%2,%3};"
                 : "+f"(d[0]), "+f"(d[1]), "+f"(d[2]), "+f"(d[3])
                 : "r"(a0), "r"(a1), "r"(a2), "r"(a3), "r"(b0), "r"(b1));
}

#define AROW 68   // fp32/tf32 smem row stride (u32)

// ---------------- degree / CSR ----------------
__global__ void k_zero(int N) {
    int i = blockIdx.x * blockDim.x + threadIdx.x;
    if (i < N) g_degi[i] = 0;
}

// count degree AND record each edge's rank within its dst row (atomic return value)
__global__ void k_hist(const int* __restrict__ ei, int E) {
    int e = blockIdx.x * blockDim.x + threadIdx.x;
    if (e < E) {
        int d = ei[E + e];
        g_erank[e] = atomicAdd(&g_degi[d], 1);
    }
}

__global__ __launch_bounds__(SCAN_T) void k_scan_local(int N) {
    __shared__ int sdata[SCAN_T];
    int base = blockIdx.x * SCAN_ITEMS;
    int i0 = base + threadIdx.x * 2;
    int d0 = (i0     < N) ? g_degi[i0]     : 0;
    int d1 = (i0 + 1 < N) ? g_degi[i0 + 1] : 0;
    int tsum = d0 + d1;
    sdata[threadIdx.x] = tsum;
    __syncthreads();
    for (int off = 1; off < SCAN_T; off <<= 1) {
        int v = (threadIdx.x >= off) ? sdata[threadIdx.x - off] : 0;
        __syncthreads();
        sdata[threadIdx.x] += v;
        __syncthreads();
    }
    int excl = sdata[threadIdx.x] - tsum;
    if (i0     < N) g_rowptr[i0]     = excl;
    if (i0 + 1 < N) g_rowptr[i0 + 1] = excl + d0;
    if (threadIdx.x == SCAN_T - 1) g_bsum[blockIdx.x] = sdata[SCAN_T - 1];
}

__global__ __launch_bounds__(SCAN_T) void k_scan_bsums(int B) {
    __shared__ int sdata[SCAN_T];
    int v = (threadIdx.x < B) ? g_bsum[threadIdx.x] : 0;
    sdata[threadIdx.x] = v;
    __syncthreads();
    for (int off = 1; off < SCAN_T; off <<= 1) {
        int p = (threadIdx.x >= off) ? sdata[threadIdx.x - off] : 0;
        __syncthreads();
        sdata[threadIdx.x] += p;
        __syncthreads();
    }
    if (threadIdx.x < B) g_bsum[threadIdx.x] = sdata[threadIdx.x] - v;
}

// merged: finish scan + compute dinv + scaled x rows
__global__ void k_scan_add_prep(const float* __restrict__ x, int N, int E) {
    int i = blockIdx.x * blockDim.x + threadIdx.x;
    if (i == 0) g_rowptr[N] = E;
    if (i >= N) return;
    g_rowptr[i] += g_bsum[i / SCAN_ITEMS];
    float di = rsqrtf((float)(g_degi[i] + 1));
    g_dinv[i] = di;
    g_xs4[i] = make_float4(di * x[(size_t)i * 3 + 0],
                           di * x[(size_t)i * 3 + 1],
                           di * x[(size_t)i * 3 + 2], 0.0f);
}

// atomic-free fill: slot = rowptr[d] + rank[e]
__global__ void k_fill(const int* __restrict__ ei, int E) {
    int e = blockIdx.x * blockDim.x + threadIdx.x;
    if (e >= E) return;
    int s = ei[e];
    int d = ei[E + e];
    g_esrc[g_rowptr[d] + g_erank[e]] = s;
}

// ---------------- tf32 tensor-core GEMM phase ----------------
__device__ __forceinline__ void gemm_mma(const uint32_t* sA, const uint32_t* sB,
                                         uint32_t* sC, const float* sdinv,
                                         __nv_bfloat16* outBuf, int nodeBase, int N) {
    int tid  = threadIdx.x;
    int w    = tid >> 5;
    int lane = tid & 31;
    int mw = w & 3;
    int nw = w >> 2;
    int g  = lane >> 2;
    int t  = lane & 3;

    float d[4][4];
    #pragma unroll
    for (int i = 0; i < 4; i++)
        #pragma unroll
        for (int j = 0; j < 4; j++) d[i][j] = 0.0f;

    const uint32_t* aRow0 = sA + (mw * 16 + g) * AROW;
    const uint32_t* aRow1 = aRow0 + 8 * AROW;
    int nbase = nw * 32 + g;

    #pragma unroll
    for (int kt = 0; kt < 8; kt++) {
        int k0 = kt * 8 + t;
        uint32_t a0 = aRow0[k0];
        uint32_t a1 = aRow1[k0];
        uint32_t a2 = aRow0[k0 + 4];
        uint32_t a3 = aRow1[k0 + 4];
        const uint32_t* b0p = sB + k0 * AROW + nbase;
        const uint32_t* b1p = b0p + 4 * AROW;
        #pragma unroll
        for (int nt = 0; nt < 4; nt++) {
            mma_tf32(d[nt], a0, a1, a2, a3, b0p[nt * 8], b1p[nt * 8]);
        }
    }

    int r0 = mw * 16 + g;
    int r1 = r0 + 8;
    float di0 = sdinv[r0], di1 = sdinv[r1];
    #pragma unroll
    for (int nt = 0; nt < 4; nt++) {
        int cp = nw * 16 + nt * 4 + t;
        sC[r0 * 36 + cp] = pack_bf16x2(d[nt][0] * di0, d[nt][1] * di0);
        sC[r1 * 36 + cp] = pack_bf16x2(d[nt][2] * di1, d[nt][3] * di1);
    }
    __syncthreads();

    int r = tid >> 2, q = tid & 3;
    if (nodeBase + r < N) {
        uint4 v0 = *(uint4*)&sC[r * 36 + q * 8];
        uint4 v1 = *(uint4*)&sC[r * 36 + q * 8 + 4];
        __nv_bfloat16* o = outBuf + (size_t)(nodeBase + r) * HDIM + q * 16;
        *(uint4*)o       = v0;
        *((uint4*)o + 1) = v1;
    }
}

__device__ __forceinline__ void load_W_tf32(const float* __restrict__ W, uint32_t* sB) {
    int tid = threadIdx.x;
    #pragma unroll
    for (int i = tid; i < 1024; i += 256) {
        int k = i >> 4, cq = i & 15;
        float4 wv = ((const float4*)W)[i];
        uint32_t* o = sB + k * AROW + cq * 4;
        o[0] = f2tf32(wv.x); o[1] = f2tf32(wv.y);
        o[2] = f2tf32(wv.z); o[3] = f2tf32(wv.w);
    }
}

__device__ __forceinline__ void load_dinv(float* sdinv, int nodeBase, int N) {
    int tid = threadIdx.x;
    if (tid >= 64 && tid < 128) {
        int n = nodeBase + tid - 64;
        sdinv[tid - 64] = (n < N) ? g_dinv[n] : 0.0f;
    }
}

// ---------------- kA: fused x-aggregation + layer-1 + layer-2 transforms -> m0 ----------------
__global__ __launch_bounds__(256) void kA_l12(const float* __restrict__ W1,
                                              const float* __restrict__ b1,
                                              const float* __restrict__ W2, int N) {
    __shared__ __align__(16) uint32_t sA[64 * AROW];
    __shared__ __align__(16) uint32_t sB[64 * AROW];
    __shared__ __align__(16) uint32_t sC[64 * 36];
    __shared__ float4 sxa[64];
    __shared__ float sW1[192];
    __shared__ float sb1[64];
    __shared__ float sdinv[64];
    int tid = threadIdx.x;
    int nodeBase = blockIdx.x * 64;

    if (tid < 64) {
        int d = nodeBase + tid;
        float4 a = make_float4(0.f, 0.f, 0.f, 0.f);
        float di = 0.0f;
        if (d < N) {
            a = g_xs4[d];
            int i = g_rowptr[d], end = g_rowptr[d + 1];
            for (; i + 2 <= end; i += 2) {
                int s0 = g_esrc[i], s1 = g_esrc[i + 1];
                float4 v0 = g_xs4[s0];
                float4 v1 = g_xs4[s1];
                a.x += v0.x + v1.x; a.y += v0.y + v1.y; a.z += v0.z + v1.z;
            }
            if (i < end) {
                float4 v = g_xs4[g_esrc[i]];
                a.x += v.x; a.y += v.y; a.z += v.z;
            }
            di = g_dinv[d];
        }
        sxa[tid] = make_float4(di * a.x, di * a.y, di * a.z, 0.0f);
    }
    if (tid >= 192) {
        int j = tid - 192;
        if (j < 64) sb1[j] = b1[j];
    }
    if (tid >= 128 && tid < 192) {
        sW1[tid - 128] = W1[tid - 128];
        sW1[tid - 64]  = W1[tid - 64];
        sW1[tid]       = W1[tid];
    }
    load_dinv(sdinv, nodeBase, N);
    load_W_tf32(W2, sB);
    __syncthreads();

    #pragma unroll
    for (int i = tid; i < 4096; i += 256) {
        int n = i >> 6, c = i & 63;
        float4 xa = sxa[n];
        float v = sb1[c] + xa.x * sW1[c] + xa.y * sW1[64 + c] + xa.z * sW1[128 + c];
        sA[n * AROW + c] = f2tf32(fmaxf(v, 0.0f));
    }
    __syncthreads();

    gemm_mma(sA, sB, sC, sdinv, g_m0, nodeBase, N);
}

// ---------------- kB: fused layer-2 aggregation + layer-3 transform -> m1 ----------------
__global__ __launch_bounds__(256) void kB_agg_tr(const float* __restrict__ b2,
                                                 const float* __restrict__ W3, int N) {
    __shared__ __align__(16) uint32_t sA[64 * AROW];
    __shared__ __align__(16) uint32_t sB[64 * AROW];
    __shared__ __align__(16) uint32_t sC[64 * 36];
    __shared__ float sb2[64];
    __shared__ float sdinv[64];
    int tid = threadIdx.x;
    int nodeBase = blockIdx.x * 64;

    if (tid < 64) sb2[tid] = b2[tid];
    load_dinv(sdinv, nodeBase, N);
    load_W_tf32(W3, sB);

    {
        int w    = tid >> 5;
        int lane = tid & 31;
        int oct  = lane >> 3;
        int l8   = lane & 7;
        #pragma unroll
        for (int j = 0; j < 2; j++) {
            int nl = w * 8 + j * 4 + oct;
            int d  = nodeBase + nl;
            float a[8] = {0.f, 0.f, 0.f, 0.f, 0.f, 0.f, 0.f, 0.f};
            float di = 0.0f;
            if (d < N) {
                acc_uint4(a, ((const uint4*)(g_m0 + (size_t)d * HDIM))[l8]);
                int i = g_rowptr[d], end = g_rowptr[d + 1];
                for (; i + 2 <= end; i += 2) {
                    int s0 = g_esrc[i], s1 = g_esrc[i + 1];
                    uint4 u0 = ((const uint4*)(g_m0 + (size_t)s0 * HDIM))[l8];
                    uint4 u1 = ((const uint4*)(g_m0 + (size_t)s1 * HDIM))[l8];
                    acc_uint4(a, u0);
                    acc_uint4(a, u1);
                }
                if (i < end) {
                    int s = g_esrc[i];
                    acc_uint4(a, ((const uint4*)(g_m0 + (size_t)s * HDIM))[l8]);
                }
                di = g_dinv[d];
            }
            const float* bb = &sb2[l8 * 8];
            uint32_t* o = sA + nl * AROW + l8 * 8;
            #pragma unroll
            for (int k = 0; k < 8; k++)
                o[k] = f2tf32(fmaxf(bb[k] + di * a[k], 0.f));
        }
    }
    __syncthreads();

    gemm_mma(sA, sB, sC, sdinv, g_m1, nodeBase, N);
}

// ---------------- kC: fused layer-3 aggregation + relu + pool partials ----------------
__global__ __launch_bounds__(256) void kC_agg_pool(const float* __restrict__ b, int N) {
    int tid  = threadIdx.x;
    int w    = tid >> 5;
    int lane = tid & 31;
    int oct  = lane >> 3;
    int l8   = lane & 7;

    float bb[8];
    #pragma unroll
    for (int k = 0; k < 8; k++) bb[k] = b[l8 * 8 + k];
    float acc[8] = {0.f, 0.f, 0.f, 0.f, 0.f, 0.f, 0.f, 0.f};

    int stride = gridDim.x * 32;
    for (int d = blockIdx.x * 32 + w * 4 + oct; d < N; d += stride) {
        float a[8] = {0.f, 0.f, 0.f, 0.f, 0.f, 0.f, 0.f, 0.f};
        acc_uint4(a, ((const uint4*)(g_m1 + (size_t)d * HDIM))[l8]);
        int i = g_rowptr[d], end = g_rowptr[d + 1];
        for (; i + 2 <= end; i += 2) {
            int s0 = g_esrc[i], s1 = g_esrc[i + 1];
            uint4 u0 = ((const uint4*)(g_m1 + (size_t)s0 * HDIM))[l8];
            uint4 u1 = ((const uint4*)(g_m1 + (size_t)s1 * HDIM))[l8];
            acc_uint4(a, u0);
            acc_uint4(a, u1);
        }
        if (i < end) {
            int s = g_esrc[i];
            acc_uint4(a, ((const uint4*)(g_m1 + (size_t)s * HDIM))[l8]);
        }
        float di = g_dinv[d];
        #pragma unroll
        for (int k = 0; k < 8; k++)
            acc[k] += fmaxf(bb[k] + di * a[k], 0.f);
    }

    __shared__ float sp[64];
    if (tid < 64) sp[tid] = 0.0f;
    __syncthreads();
    #pragma unroll
    for (int k = 0; k < 8; k++)
        atomicAdd(&sp[l8 * 8 + k], acc[k]);
    __syncthreads();
    if (tid < 64) g_partial[(size_t)blockIdx.x * HDIM + tid] = sp[tid];
}

__global__ __launch_bounds__(256) void k_reduce(int numPartial) {
    __shared__ float sdata[256];
    int c = blockIdx.x;
    float s = 0.0f;
    for (int i = threadIdx.x; i < numPartial; i += 256)
        s += g_partial[(size_t)i * HDIM + c];
    sdata[threadIdx.x] = s;
    __syncthreads();
    for (int off = 128; off > 0; off >>= 1) {
        if (threadIdx.x < off) sdata[threadIdx.x] += sdata[threadIdx.x + off];
        __syncthreads();
    }
    if (threadIdx.x == 0) g_pool[c] = sdata[0];
}

__global__ void k_final(const float* __restrict__ Wfc, const float* __restrict__ bfc,
                        float* __restrict__ out, int N) {
    int c = threadIdx.x;
    if (c >= 24) return;
    float invN = 1.0f / (float)N;
    float acc = bfc[c];
    #pragma unroll
    for (int k = 0; k < 64; k++)
        acc += (g_pool[k] * invN) * Wfc[k * 24 + c];
    out[c] = tanhf(acc);
}

// ---------------- launch ----------------
extern "C" void kernel_launch(void* const* d_in, const int* in_sizes, int n_in,
                              void* d_out, int out_size) {
    const float* x   = (const float*)d_in[0];
    const int*   ei  = (const int*)d_in[1];   // int32 (JAX x64 disabled)
    const float* W1  = (const float*)d_in[3];
    const float* b1  = (const float*)d_in[4];
    const float* W2  = (const float*)d_in[5];
    const float* b2  = (const float*)d_in[6];
    const float* W3  = (const float*)d_in[7];
    const float* b3  = (const float*)d_in[8];
    const float* Wfc = (const float*)d_in[9];
    const float* bfc = (const float*)d_in[10];
    float* out = (float*)d_out;

    int N = in_sizes[0] / 3;
    int E = in_sizes[1] / 2;

    const int T = 256;
    int nbN    = (N + T - 1) / T;
    int nbE    = (E + T - 1) / T;
    int nbTr   = (N + 63) / 64;
    int nbScan = (N + SCAN_ITEMS - 1) / SCAN_ITEMS;

    // CSR + normalization
    k_zero<<<nbN, T>>>(N);
    k_hist<<<nbE, T>>>(ei, E);
    k_scan_local<<<nbScan, SCAN_T>>>(N);
    k_scan_bsums<<<1, SCAN_T>>>(nbScan);
    k_scan_add_prep<<<nbN, T>>>(x, N, E);
    k_fill<<<nbE, T>>>(ei, E);

    // fused x-agg + layer1 + layer2 transforms -> m0 (tf32 tensor cores)
    kA_l12<<<nbTr, T>>>(W1, b1, W2, N);

    // fused layer2 aggregation + layer3 transform -> m1 (tf32 tensor cores)
    kB_agg_tr<<<nbTr, T>>>(b2, W3, N);

    // fused layer3 aggregation + relu + mean-pool
    kC_agg_pool<<<POOL_BLOCKS, T>>>(b3, N);

    // reduce + FC + tanh
    k_reduce<<<64, 256>>>(POOL_BLOCKS);
    k_final<<<1, 32>>>(Wfc, bfc, out, N);
}